// round 3
// baseline (speedup 1.0000x reference)
#include <cuda_runtime.h>
#include <math.h>

#define DIM   4096
#define CAP   8192
#define TOPK  8
#define NV4   (DIM / 4)          // 1024 float4 per row

// Scratch (no allocations allowed in kernel_launch).
__device__ float g_weighted[CAP];
__device__ float g_retrieved[DIM];
__device__ int   g_done = 0;     // block-completion counter (reset by last block)

// ---------------------------------------------------------------------------
// Kernel 1: fused score + topk + gather.
// Block-per-row score pass (best measured shape). The LAST block to finish
// (fence + atomic counter) additionally computes top-8 and the mean of the
// retrieved rows -> g_retrieved. Deterministic: result depends only on data.
// ---------------------------------------------------------------------------
__global__ __launch_bounds__(256) void score_topk_kernel(
    const float* __restrict__ q,
    const float* __restrict__ mb,
    const float* __restrict__ imp,
    const float* __restrict__ age)
{
    const int row = blockIdx.x;
    const int tid = threadIdx.x;
    const float4* m  = reinterpret_cast<const float4*>(mb) + (size_t)row * NV4;
    const float4* qv = reinterpret_cast<const float4*>(q);

    // ---- score: 4 float4 per thread, fully unrolled, streaming loads ----
    float dot = 0.f, mn2 = 0.f, qn2 = 0.f;
    #pragma unroll
    for (int u = 0; u < 4; u++) {
        int i = tid + u * 256;
        float4 a = __ldcs(&m[i]);       // evict-first: 128 MiB one-shot stream
        float4 b = qv[i];               // q is hot in L1/L2
        dot += a.x * b.x + a.y * b.y + a.z * b.z + a.w * b.w;
        mn2 += a.x * a.x + a.y * a.y + a.z * a.z + a.w * a.w;
        qn2 += b.x * b.x + b.y * b.y + b.z * b.z + b.w * b.w;
    }

    #pragma unroll
    for (int o = 16; o > 0; o >>= 1) {
        dot += __shfl_down_sync(0xffffffffu, dot, o);
        mn2 += __shfl_down_sync(0xffffffffu, mn2, o);
        qn2 += __shfl_down_sync(0xffffffffu, qn2, o);
    }

    __shared__ float s0[8], s1[8], s2[8];
    const int w = tid >> 5;
    if ((tid & 31) == 0) { s0[w] = dot; s1[w] = mn2; s2[w] = qn2; }
    __syncthreads();

    __shared__ int s_last;
    if (tid == 0) {
        float d = 0.f, m2 = 0.f, q2 = 0.f;
        #pragma unroll
        for (int i = 0; i < 8; i++) { d += s0[i]; m2 += s1[i]; q2 += s2[i]; }
        float sim = d / fmaxf(sqrtf(q2) * sqrtf(m2), 1e-8f);
        g_weighted[row] = sim * imp[row] * expf(-0.001f * age[row]);
        __threadfence();                         // publish score before counting
        int old = atomicAdd(&g_done, 1);
        s_last = (old == gridDim.x - 1);
    }
    __syncthreads();
    if (!s_last) return;

    // =======================================================================
    // LAST BLOCK ONLY: top-8 + gather. All 8192 scores are visible (every
    // writer fenced before its atomicAdd; our add observed all of them).
    // =======================================================================

    // Each thread owns 32 scores: indices tid + 256*j (coalesced ldcg).
    float v[32];
    #pragma unroll
    for (int j = 0; j < 32; j++)
        v[j] = __ldcg(&g_weighted[tid + 256 * j]);

    __shared__ float s_wmax[8];
    __shared__ float s_gmax;
    __shared__ int   s_arg;
    __shared__ int   s_idx[TOPK];

    for (int k = 0; k < TOPK; k++) {
        // local max over registers
        float mx = -3.0e38f;
        #pragma unroll
        for (int j = 0; j < 32; j++) mx = fmaxf(mx, v[j]);
        // warp max
        #pragma unroll
        for (int o = 16; o > 0; o >>= 1)
            mx = fmaxf(mx, __shfl_xor_sync(0xffffffffu, mx, o));
        if ((tid & 31) == 0) s_wmax[tid >> 5] = mx;
        if (tid == 0) s_arg = 0x7fffffff;
        __syncthreads();
        if (tid == 0) {
            float g = s_wmax[0];
            #pragma unroll
            for (int j = 1; j < 8; j++) g = fmaxf(g, s_wmax[j]);
            s_gmax = g;
        }
        __syncthreads();
        // find owning index (min index on ties == jax top_k tie order)
        float g = s_gmax;
        #pragma unroll
        for (int j = 0; j < 32; j++)
            if (v[j] == g) atomicMin(&s_arg, tid + 256 * j);
        __syncthreads();
        int win = s_arg;
        if (tid == 0) s_idx[k] = win;
        // exclude the single winner
        if ((win & 255) == tid) v[(win - tid) >> 8] = -3.0e38f;
        __syncthreads();
    }

    // gather: retrieved = mean of the 8 selected rows (4 float4 per thread)
    const float4* mbv = reinterpret_cast<const float4*>(mb);
    #pragma unroll
    for (int u = 0; u < 4; u++) {
        int j = tid + u * 256;
        float4 acc = make_float4(0.f, 0.f, 0.f, 0.f);
        #pragma unroll
        for (int t = 0; t < TOPK; t++) {
            float4 x = __ldg(&mbv[(size_t)s_idx[t] * NV4 + j]);
            acc.x += x.x; acc.y += x.y; acc.z += x.z; acc.w += x.w;
        }
        reinterpret_cast<float4*>(g_retrieved)[j] =
            make_float4(acc.x * 0.125f, acc.y * 0.125f, acc.z * 0.125f, acc.w * 0.125f);
    }

    if (tid == 0) g_done = 0;   // reset for next graph replay
}

// ---------------------------------------------------------------------------
// Kernel 2: decode GEMV, block-per-row. out[i] = dot(W_dec[i,:], retrieved)+b[i]
// ---------------------------------------------------------------------------
__global__ __launch_bounds__(256) void gemv_kernel(
    const float* __restrict__ W,
    const float* __restrict__ b,
    float* __restrict__ out)
{
    const int row = blockIdx.x;
    const int tid = threadIdx.x;
    const float4* wr = reinterpret_cast<const float4*>(W) + (size_t)row * NV4;
    const float4* rv = reinterpret_cast<const float4*>(g_retrieved);

    float acc = 0.f;
    #pragma unroll
    for (int u = 0; u < 4; u++) {
        int i = tid + u * 256;
        float4 a = __ldcs(&wr[i]);      // evict-first: 64 MiB one-shot stream
        float4 v = rv[i];               // retrieved hot in L1/L2
        acc += a.x * v.x + a.y * v.y + a.z * v.z + a.w * v.w;
    }
    #pragma unroll
    for (int o = 16; o > 0; o >>= 1)
        acc += __shfl_down_sync(0xffffffffu, acc, o);

    __shared__ float s[8];
    const int w = tid >> 5;
    if ((tid & 31) == 0) s[w] = acc;
    __syncthreads();
    if (tid == 0) {
        float t = 0.f;
        #pragma unroll
        for (int i = 0; i < 8; i++) t += s[i];
        out[row] = t + b[row];
    }
}

// ---------------------------------------------------------------------------
extern "C" void kernel_launch(void* const* d_in, const int* in_sizes, int n_in,
                              void* d_out, int out_size)
{
    const float* q   = (const float*)d_in[0];  // [4096]
    const float* mb  = (const float*)d_in[1];  // [8192, 4096]
    const float* imp = (const float*)d_in[2];  // [8192]
    const float* age = (const float*)d_in[3];  // [8192]
    const float* W   = (const float*)d_in[4];  // [4096, 4096]
    const float* b   = (const float*)d_in[5];  // [4096]
    float* out = (float*)d_out;                // [4096]

    score_topk_kernel<<<CAP, 256>>>(q, mb, imp, age);
    gemv_kernel<<<DIM, 256>>>(W, b, out);
}

// round 6
// speedup vs baseline: 1.2979x; 1.2979x over previous
#include <cuda_runtime.h>
#include <math.h>

#define DIM   4096
#define CAP   8192
#define TOPK  8
#define NV4   (DIM / 4)          // 1024 float4 per row

// Scratch (no allocations allowed in kernel_launch).
__device__ float g_weighted[CAP];
__device__ int   g_topidx[TOPK];
__device__ float g_retrieved[DIM];

// ---------------------------------------------------------------------------
// Kernel 1: fused score pass. Block-per-row (best measured shape).
// mb is a one-shot 128 MiB stream -> __ldcs (evict-first) so it does NOT
// evict W_dec from L2 between graph replays. q is hot in L1.
// ---------------------------------------------------------------------------
__global__ __launch_bounds__(256) void score_kernel(
    const float* __restrict__ q,
    const float* __restrict__ mb,
    const float* __restrict__ imp,
    const float* __restrict__ age)
{
    const int row = blockIdx.x;
    const int tid = threadIdx.x;
    const float4* m  = reinterpret_cast<const float4*>(mb) + (size_t)row * NV4;
    const float4* qv = reinterpret_cast<const float4*>(q);

    float dot = 0.f, mn2 = 0.f, qn2 = 0.f;
    #pragma unroll
    for (int u = 0; u < 4; u++) {
        int i = tid + u * 256;
        float4 a = __ldcs(&m[i]);   // streaming: evict-first
        float4 b = qv[i];
        dot += a.x * b.x + a.y * b.y + a.z * b.z + a.w * b.w;
        mn2 += a.x * a.x + a.y * a.y + a.z * a.z + a.w * a.w;
        qn2 += b.x * b.x + b.y * b.y + b.z * b.z + b.w * b.w;
    }

    #pragma unroll
    for (int o = 16; o > 0; o >>= 1) {
        dot += __shfl_down_sync(0xffffffffu, dot, o);
        mn2 += __shfl_down_sync(0xffffffffu, mn2, o);
        qn2 += __shfl_down_sync(0xffffffffu, qn2, o);
    }

    __shared__ float s0[8], s1[8], s2[8];
    const int w = tid >> 5;
    if ((tid & 31) == 0) { s0[w] = dot; s1[w] = mn2; s2[w] = qn2; }
    __syncthreads();

    if (tid == 0) {
        float d = 0.f, m2 = 0.f, q2 = 0.f;
        #pragma unroll
        for (int i = 0; i < 8; i++) { d += s0[i]; m2 += s1[i]; q2 += s2[i]; }
        float sim = d / fmaxf(sqrtf(q2) * sqrtf(m2), 1e-8f);
        g_weighted[row] = sim * imp[row] * expf(-0.001f * age[row]);
    }
}

// ---------------------------------------------------------------------------
// Kernel 2: top-8 of 8192 + gather/mean, fused. Single block of 1024 threads.
// ---------------------------------------------------------------------------
__global__ __launch_bounds__(1024) void topk_gather_kernel(const float* __restrict__ mb)
{
    __shared__ float w[CAP];          // 32 KB
    __shared__ float bv[32];
    __shared__ int   bi[32];
    __shared__ int   s_idx[TOPK];

    const int tid = threadIdx.x;
    for (int i = tid; i < CAP; i += 1024) w[i] = g_weighted[i];
    __syncthreads();

    for (int k = 0; k < TOPK; k++) {
        float best = -3.0e38f;
        int   idx  = -1;
        #pragma unroll
        for (int i = tid; i < CAP; i += 1024) {
            float v = w[i];
            if (v > best) { best = v; idx = i; }   // strict > keeps min index on ties
        }
        #pragma unroll
        for (int o = 16; o > 0; o >>= 1) {
            float ov = __shfl_down_sync(0xffffffffu, best, o);
            int   oi = __shfl_down_sync(0xffffffffu, idx, o);
            if (ov > best || (ov == best && oi < idx)) { best = ov; idx = oi; }
        }
        if ((tid & 31) == 0) { bv[tid >> 5] = best; bi[tid >> 5] = idx; }
        __syncthreads();
        if (tid == 0) {
            float bb = bv[0]; int ii = bi[0];
            #pragma unroll
            for (int j = 1; j < 32; j++)
                if (bv[j] > bb || (bv[j] == bb && bi[j] < ii)) { bb = bv[j]; ii = bi[j]; }
            s_idx[k] = ii;
            g_topidx[k] = ii;
            w[ii] = -3.0e38f;           // exclude from next pass
        }
        __syncthreads();
    }

    // gather: retrieved = mean of the 8 selected rows (1 float4 per thread)
    const float4* mbv = reinterpret_cast<const float4*>(mb);
    const int j = tid;                  // 0..1023 float4 lanes
    float4 acc = make_float4(0.f, 0.f, 0.f, 0.f);
    #pragma unroll
    for (int t = 0; t < TOPK; t++) {
        float4 x = __ldg(&mbv[(size_t)s_idx[t] * NV4 + j]);
        acc.x += x.x; acc.y += x.y; acc.z += x.z; acc.w += x.w;
    }
    reinterpret_cast<float4*>(g_retrieved)[j] =
        make_float4(acc.x * 0.125f, acc.y * 0.125f, acc.z * 0.125f, acc.w * 0.125f);
}

// ---------------------------------------------------------------------------
// Kernel 3: decode GEMV, block-per-row. W_dec (64 MiB) is read with DEFAULT
// caching so it stays L2-resident across graph replays (L2 is 126 MB and not
// flushed per launch; the mb stream is ldcs so it won't evict W).
// ---------------------------------------------------------------------------
__global__ __launch_bounds__(256) void gemv_kernel(
    const float* __restrict__ W,
    const float* __restrict__ b,
    float* __restrict__ out)
{
    const int row = blockIdx.x;
    const int tid = threadIdx.x;
    const float4* wr = reinterpret_cast<const float4*>(W) + (size_t)row * NV4;
    const float4* rv = reinterpret_cast<const float4*>(g_retrieved);

    float acc = 0.f;
    #pragma unroll
    for (int u = 0; u < 4; u++) {
        int i = tid + u * 256;
        float4 a = __ldg(&wr[i]);       // default policy: L2-resident steady state
        float4 v = rv[i];
        acc += a.x * v.x + a.y * v.y + a.z * v.z + a.w * v.w;
    }
    #pragma unroll
    for (int o = 16; o > 0; o >>= 1)
        acc += __shfl_down_sync(0xffffffffu, acc, o);

    __shared__ float s[8];
    const int w = tid >> 5;
    if ((tid & 31) == 0) s[w] = acc;
    __syncthreads();
    if (tid == 0) {
        float t = 0.f;
        #pragma unroll
        for (int i = 0; i < 8; i++) t += s[i];
        out[row] = t + b[row];
    }
}

// ---------------------------------------------------------------------------
extern "C" void kernel_launch(void* const* d_in, const int* in_sizes, int n_in,
                              void* d_out, int out_size)
{
    const float* q   = (const float*)d_in[0];  // [4096]
    const float* mb  = (const float*)d_in[1];  // [8192, 4096]
    const float* imp = (const float*)d_in[2];  // [8192]
    const float* age = (const float*)d_in[3];  // [8192]
    const float* W   = (const float*)d_in[4];  // [4096, 4096]
    const float* b   = (const float*)d_in[5];  // [4096]
    float* out = (float*)d_out;                // [4096]

    score_kernel<<<CAP, 256>>>(q, mb, imp, age);
    topk_gather_kernel<<<1, 1024>>>(mb);
    gemv_kernel<<<DIM, 256>>>(W, b, out);
}

// round 7
// speedup vs baseline: 1.3813x; 1.0642x over previous
#include <cuda_runtime.h>
#include <math.h>

#define DIM   4096
#define CAP   8192
#define TOPK  8
#define NV4   (DIM / 4)          // 1024 float4 per row

// Scratch (no allocations allowed in kernel_launch).
__device__ float g_weighted[CAP];
__device__ int   g_topidx[TOPK];
__device__ float g_retrieved[DIM];

// ---------------------------------------------------------------------------
// Kernel 1: fused score pass, 2 ROWS PER BLOCK. Interleaved streaming loads
// (8 independent LDCS.128 per thread) amortize the reduction tail over 32 KB.
// mb is a one-shot 128 MiB stream -> __ldcs so it won't evict W_dec from L2.
// ---------------------------------------------------------------------------
__global__ __launch_bounds__(256) void score_kernel(
    const float* __restrict__ q,
    const float* __restrict__ mb,
    const float* __restrict__ imp,
    const float* __restrict__ age)
{
    const int r0  = blockIdx.x * 2;
    const int r1  = r0 + 1;
    const int tid = threadIdx.x;
    const float4* m0 = reinterpret_cast<const float4*>(mb) + (size_t)r0 * NV4;
    const float4* m1 = reinterpret_cast<const float4*>(mb) + (size_t)r1 * NV4;
    const float4* qv = reinterpret_cast<const float4*>(q);

    float d0 = 0.f, n0 = 0.f, d1 = 0.f, n1 = 0.f, qn = 0.f;
    #pragma unroll
    for (int u = 0; u < 4; u++) {
        int i = tid + u * 256;
        float4 a0 = __ldcs(&m0[i]);
        float4 a1 = __ldcs(&m1[i]);
        float4 b  = qv[i];
        d0 += a0.x * b.x + a0.y * b.y + a0.z * b.z + a0.w * b.w;
        n0 += a0.x * a0.x + a0.y * a0.y + a0.z * a0.z + a0.w * a0.w;
        d1 += a1.x * b.x + a1.y * b.y + a1.z * b.z + a1.w * b.w;
        n1 += a1.x * a1.x + a1.y * a1.y + a1.z * a1.z + a1.w * a1.w;
        qn += b.x * b.x + b.y * b.y + b.z * b.z + b.w * b.w;
    }

    #pragma unroll
    for (int o = 16; o > 0; o >>= 1) {
        d0 += __shfl_down_sync(0xffffffffu, d0, o);
        n0 += __shfl_down_sync(0xffffffffu, n0, o);
        d1 += __shfl_down_sync(0xffffffffu, d1, o);
        n1 += __shfl_down_sync(0xffffffffu, n1, o);
        qn += __shfl_down_sync(0xffffffffu, qn, o);
    }

    __shared__ float s0[8], s1[8], s2[8], s3[8], s4[8];
    const int w = tid >> 5;
    if ((tid & 31) == 0) { s0[w] = d0; s1[w] = n0; s2[w] = d1; s3[w] = n1; s4[w] = qn; }
    __syncthreads();

    if (tid == 0) {
        float D0 = 0.f, N0 = 0.f, D1 = 0.f, N1 = 0.f, Q = 0.f;
        #pragma unroll
        for (int i = 0; i < 8; i++) {
            D0 += s0[i]; N0 += s1[i]; D1 += s2[i]; N1 += s3[i]; Q += s4[i];
        }
        float qs = sqrtf(Q);
        float sim0 = D0 / fmaxf(qs * sqrtf(N0), 1e-8f);
        float sim1 = D1 / fmaxf(qs * sqrtf(N1), 1e-8f);
        g_weighted[r0] = sim0 * imp[r0] * expf(-0.001f * age[r0]);
        g_weighted[r1] = sim1 * imp[r1] * expf(-0.001f * age[r1]);
    }
}

// ---------------------------------------------------------------------------
// Kernel 2: top-8 of 8192 + gather/mean, fused. Single block of 1024 threads.
// ---------------------------------------------------------------------------
__global__ __launch_bounds__(1024) void topk_gather_kernel(const float* __restrict__ mb)
{
    __shared__ float w[CAP];          // 32 KB
    __shared__ float bv[32];
    __shared__ int   bi[32];
    __shared__ int   s_idx[TOPK];

    const int tid = threadIdx.x;
    for (int i = tid; i < CAP; i += 1024) w[i] = g_weighted[i];
    __syncthreads();

    for (int k = 0; k < TOPK; k++) {
        float best = -3.0e38f;
        int   idx  = -1;
        #pragma unroll
        for (int i = tid; i < CAP; i += 1024) {
            float v = w[i];
            if (v > best) { best = v; idx = i; }   // strict > keeps min index on ties
        }
        #pragma unroll
        for (int o = 16; o > 0; o >>= 1) {
            float ov = __shfl_down_sync(0xffffffffu, best, o);
            int   oi = __shfl_down_sync(0xffffffffu, idx, o);
            if (ov > best || (ov == best && oi < idx)) { best = ov; idx = oi; }
        }
        if ((tid & 31) == 0) { bv[tid >> 5] = best; bi[tid >> 5] = idx; }
        __syncthreads();
        if (tid == 0) {
            float bb = bv[0]; int ii = bi[0];
            #pragma unroll
            for (int j = 1; j < 32; j++)
                if (bv[j] > bb || (bv[j] == bb && bi[j] < ii)) { bb = bv[j]; ii = bi[j]; }
            s_idx[k] = ii;
            g_topidx[k] = ii;
            w[ii] = -3.0e38f;           // exclude from next pass
        }
        __syncthreads();
    }

    // gather: retrieved = mean of the 8 selected rows (1 float4 per thread)
    const float4* mbv = reinterpret_cast<const float4*>(mb);
    const int j = tid;                  // 0..1023 float4 lanes
    float4 acc = make_float4(0.f, 0.f, 0.f, 0.f);
    #pragma unroll
    for (int t = 0; t < TOPK; t++) {
        float4 x = __ldg(&mbv[(size_t)s_idx[t] * NV4 + j]);
        acc.x += x.x; acc.y += x.y; acc.z += x.z; acc.w += x.w;
    }
    reinterpret_cast<float4*>(g_retrieved)[j] =
        make_float4(acc.x * 0.125f, acc.y * 0.125f, acc.z * 0.125f, acc.w * 0.125f);
}

// ---------------------------------------------------------------------------
// Kernel 3: decode GEMV, 2 ROWS PER BLOCK. W_dec read with DEFAULT caching so
// it stays L2-resident across graph replays (mb stream is ldcs -> no thrash).
// ---------------------------------------------------------------------------
__global__ __launch_bounds__(256) void gemv_kernel(
    const float* __restrict__ W,
    const float* __restrict__ b,
    float* __restrict__ out)
{
    const int r0  = blockIdx.x * 2;
    const int r1  = r0 + 1;
    const int tid = threadIdx.x;
    const float4* w0 = reinterpret_cast<const float4*>(W) + (size_t)r0 * NV4;
    const float4* w1 = reinterpret_cast<const float4*>(W) + (size_t)r1 * NV4;
    const float4* rv = reinterpret_cast<const float4*>(g_retrieved);

    float a0 = 0.f, a1 = 0.f;
    #pragma unroll
    for (int u = 0; u < 4; u++) {
        int i = tid + u * 256;
        float4 x0 = __ldg(&w0[i]);
        float4 x1 = __ldg(&w1[i]);
        float4 v  = rv[i];
        a0 += x0.x * v.x + x0.y * v.y + x0.z * v.z + x0.w * v.w;
        a1 += x1.x * v.x + x1.y * v.y + x1.z * v.z + x1.w * v.w;
    }
    #pragma unroll
    for (int o = 16; o > 0; o >>= 1) {
        a0 += __shfl_down_sync(0xffffffffu, a0, o);
        a1 += __shfl_down_sync(0xffffffffu, a1, o);
    }

    __shared__ float sa[8], sb[8];
    const int w = tid >> 5;
    if ((tid & 31) == 0) { sa[w] = a0; sb[w] = a1; }
    __syncthreads();
    if (tid == 0) {
        float t0 = 0.f, t1 = 0.f;
        #pragma unroll
        for (int i = 0; i < 8; i++) { t0 += sa[i]; t1 += sb[i]; }
        out[r0] = t0 + b[r0];
        out[r1] = t1 + b[r1];
    }
}

// ---------------------------------------------------------------------------
extern "C" void kernel_launch(void* const* d_in, const int* in_sizes, int n_in,
                              void* d_out, int out_size)
{
    const float* q   = (const float*)d_in[0];  // [4096]
    const float* mb  = (const float*)d_in[1];  // [8192, 4096]
    const float* imp = (const float*)d_in[2];  // [8192]
    const float* age = (const float*)d_in[3];  // [8192]
    const float* W   = (const float*)d_in[4];  // [4096, 4096]
    const float* b   = (const float*)d_in[5];  // [4096]
    float* out = (float*)d_out;                // [4096]

    score_kernel<<<CAP / 2, 256>>>(q, mb, imp, age);
    topk_gather_kernel<<<1, 1024>>>(mb);
    gemv_kernel<<<DIM / 2, 256>>>(W, b, out);
}